// round 11
// baseline (speedup 1.0000x reference)
#include <cuda_runtime.h>
#include <cstdint>

#define N_BOX 16384
#define FEAT 512
#define NUM_CATS 65
#define KSEL 25
#define MAX_DETS 1000
#define NMS_THRESH 0.6f
#define MIN_RPN 0.9f
#define MIN_AREA 220.0f
#define FLAG_WORDS 512      /* 16384/32 */
#define CAP 4096            /* hard cap on boxes passing score gate */
#define RW  (CAP / 32)      /* 128 words per matrix row */

#define NBUCK 4096
#define BUCK_SHIFT 9
#define BUCK_BASE 0x3F666666u   /* bits of 0.9f; scores in [0.9,1) share one exponent */

// ---------------- device scratch ----------------
__device__ int    g_M;
__device__ int    g_sortedIdx[CAP];
__device__ float4 g_sortedBox[CAP];
__device__ float  g_areaArr[CAP];
__device__ unsigned long long g_keys[CAP];     // sort keys (global: keeps kPrep smem < 48KB)
__device__ unsigned g_mat[(size_t)CAP * RW];   // suppression bitmask, words w >= i>>5 (bits j>i)

typedef unsigned long long u64;

// ================= kernel 1: compact + counting sort + gather =================
__global__ __launch_bounds__(1024, 1)
void kPrep(const float* __restrict__ roi_scores,
           const float* __restrict__ det_boxes) {
    __shared__ int sBase[NBUCK];               // 16 KB
    __shared__ int sCur[NBUCK];                // 16 KB (count, then cursor)
    __shared__ int s_wsum[32];
    __shared__ int s_M;

    const int tid  = threadIdx.x;
    const int lane = tid & 31;
    const int wid  = tid >> 5;                 // 32 warps

    #pragma unroll
    for (int k = 0; k < 4; ++k) sCur[tid * 4 + k] = 0;
    __syncthreads();

    // ---- phase 1: histogram of passing scores ----
    #pragma unroll
    for (int it = 0; it < N_BOX / 1024; ++it) {
        int i = tid + it * 1024;
        float s = roi_scores[i];
        if (s >= MIN_RPN) {
            unsigned bits = __float_as_uint(s);
            int b = min((int)((bits - BUCK_BASE) >> BUCK_SHIFT), NBUCK - 1);
            atomicAdd(&sCur[b], 1);
        }
    }
    __syncthreads();

    // ---- phase 2: exclusive scan in DESCENDING bucket order ----
    {
        int c[4], sum = 0;
        #pragma unroll
        for (int k = 0; k < 4; ++k) {
            int b = NBUCK - 1 - (tid * 4 + k);
            c[k] = sCur[b];
            sum += c[k];
        }
        int v = sum;
        #pragma unroll
        for (int off = 1; off < 32; off <<= 1) {
            int n = __shfl_up_sync(0xffffffffu, v, off);
            if (lane >= off) v += n;
        }
        if (lane == 31) s_wsum[wid] = v;
        __syncthreads();
        if (wid == 0) {
            int w = s_wsum[lane];
            #pragma unroll
            for (int off = 1; off < 32; off <<= 1) {
                int n = __shfl_up_sync(0xffffffffu, w, off);
                if (lane >= off) w += n;
            }
            s_wsum[lane] = w;
        }
        __syncthreads();
        int base = ((wid > 0) ? s_wsum[wid - 1] : 0) + (v - sum);  // exclusive for this thread
        #pragma unroll
        for (int k = 0; k < 4; ++k) {
            int b = NBUCK - 1 - (tid * 4 + k);
            sBase[b] = base;
            base += c[k];
        }
        if (tid == 0) s_M = min(s_wsum[31], CAP);
    }
    __syncthreads();
    const int M = s_M;
    if (tid == 0) g_M = M;
    #pragma unroll
    for (int k = 0; k < 4; ++k) {
        int b = tid * 4 + k;
        sCur[b] = sBase[b];                    // cursor = base
    }
    __syncthreads();

    // ---- phase 3: scatter keys to (nearly) sorted positions ----
    #pragma unroll
    for (int it = 0; it < N_BOX / 1024; ++it) {
        int i = tid + it * 1024;
        float s = roi_scores[i];
        if (s >= MIN_RPN) {
            unsigned bits = __float_as_uint(s);
            int b = min((int)((bits - BUCK_BASE) >> BUCK_SHIFT), NBUCK - 1);
            int pos = atomicAdd(&sCur[b], 1);
            if (pos < CAP)
                g_keys[pos] = ((u64)(0xFFFFFFFFu - bits) << 32) | (unsigned)i;
        }
    }
    __syncthreads();   // also fences block-visible global writes

    // ---- phase 4: fixup multi-occupancy buckets (exact (score desc, idx asc) order) ----
    #pragma unroll
    for (int k = 0; k < 4; ++k) {
        int b = tid * 4 + k;
        int st = sBase[b];
        int en = (b > 0) ? sBase[b - 1] : M;   // descending layout: next-lower bucket's base
        if (en > CAP) en = CAP;
        if (en - st > 1) {
            for (int a = st + 1; a < en; ++a) { // insertion sort (ascending keys)
                u64 key = g_keys[a];
                int p = a - 1;
                while (p >= st && g_keys[p] > key) { g_keys[p + 1] = g_keys[p]; --p; }
                g_keys[p + 1] = key;
            }
        }
    }
    __syncthreads();

    // ---- phase 5: gather boxes in sorted order ----
    for (int t = tid; t < M; t += 1024) {
        u64 key = g_keys[t];
        int orig = (int)(key & 0xFFFFFFFFu);
        g_sortedIdx[t] = orig;
        float4 b = ((const float4*)det_boxes)[orig];   // [y1, x1, y2, x2]
        g_sortedBox[t] = b;
        g_areaArr[t] = (b.w - b.y) * (b.z - b.x);      // (x2-x1)*(y2-y1)
    }
}

// ================= kernel 2: triangular suppression bitmask (diag incl.) =================
__global__ void kMatrix() {
    const int M  = g_M;
    const int Mw = (M + 31) >> 5;
    const int total = M * Mw;
    const int stride = gridDim.x * blockDim.x;
    for (int it = blockIdx.x * blockDim.x + threadIdx.x; it < total; it += stride) {
        int i = it / Mw;
        int w = it - i * Mw;
        if (w < (i >> 5)) continue;          // words w >= i>>5; bits restricted to j > i
        float4 bi = g_sortedBox[i];
        float  ai = g_areaArr[i];
        unsigned bits = 0;
        int j0 = w * 32;
        int jend = min(32, M - j0);
        int jstart = (j0 <= i) ? (i - j0 + 1) : 0;   // diagonal word: only j > i
        for (int jj = jstart; jj < jend; ++jj) {
            float4 bj = g_sortedBox[j0 + jj];
            // raw intersection extents; clamped inter > 0 <=> iw > 0 && ih > 0,
            // and when both positive the product is bit-identical to the clamped one
            float iw = fminf(bi.w, bj.w) - fmaxf(bi.y, bj.y);
            float ih = fminf(bi.z, bj.z) - fmaxf(bi.x, bj.x);
            if (iw > 0.0f && ih > 0.0f) {
                float inter = iw * ih;
                float iou = inter / (ai + g_areaArr[j0 + jj] - inter + 1e-12f);
                if (iou > NMS_THRESH) bits |= (1u << jj);
            }
        }
        g_mat[(size_t)i * RW + w] = bits;
    }
}

// ================= kernel 3: 64-box-chunk scan + select + GEMM + sort + outputs =================
#define NTHR 512
#define XK 8    /* max cross words per warp: RW/16 */

__global__ __launch_bounds__(NTHR, 1)
void kFinal(const float* __restrict__ roi_boxes,
            const float* __restrict__ det_boxes,
            const float* __restrict__ vis,
            const float* __restrict__ img_info,
            const float* __restrict__ txt,
            float* __restrict__ out) {
    __shared__ unsigned s_removed[RW];
    __shared__ unsigned s_keepw[RW];
    __shared__ unsigned s_flags[FLAG_WORDS];
    __shared__ int      s_scan[FLAG_WORDS];
    __shared__ int      s_wsum[16];
    __shared__ unsigned s_kmlo, s_kmhi;
    __shared__ int      s_cnt;
    __shared__ int      s_count;
    __shared__ int      s_selidx[KSEL];
    __shared__ float    S[KSEL][NUM_CATS];
    __shared__ float    s_key[KSEL];
    __shared__ int      s_src[KSEL];
    __shared__ unsigned char s_fgv[KSEL];

    const int tid  = threadIdx.x;
    const int lane = tid & 31;
    const int wid  = tid >> 5;          // 16 warps
    const int M    = g_M;
    const int Mw   = (M + 31) >> 5;
    const int Mc   = (M + 63) >> 6;     // 64-box chunks

    for (int t = tid; t < RW; t += NTHR) { s_removed[t] = 0; s_keepw[t] = 0; }
    for (int t = tid; t < FLAG_WORDS; t += NTHR) s_flags[t] = 0;
    if (tid == 0) s_cnt = 0;
    __syncthreads();

    // ---- chunked greedy NMS scan with speculative cross prefetch ----
    {
        // warp0's diag registers for current chunk (lane holds its own rows' words)
        unsigned d0lo = 0, d0hi = 0, d1hi = 0;
        if (wid == 0 && Mc > 0) {
            int r0 = lane, r1 = 32 + lane;
            if (r0 < M) { d0lo = g_mat[(size_t)r0 * RW + 0];
                          if (1 < Mw) d0hi = g_mat[(size_t)r0 * RW + 1]; }
            if (r1 < M && 1 < Mw) d1hi = g_mat[(size_t)r1 * RW + 1];
        }

        for (int c = 0; c < Mc; ++c) {
            const int base = c * 64;
            const int lim  = M - base;                 // >0

            // ALL warps: speculative prefetch of this chunk's cross words
            // (km unknown yet; masked after the barrier — unkept/garbage rows drop out)
            unsigned plo[XK], phi[XK];
            {
                const int rlo = base + lane;           // <= CAP-1 always
                const int rhi = base + 32 + lane;      // <= CAP-1 always
                #pragma unroll
                for (int k = 0; k < XK; ++k) {
                    int w = 2 * c + 2 + wid + 16 * k;
                    plo[k] = 0; phi[k] = 0;
                    if (w < Mw) {
                        plo[k] = g_mat[(size_t)rlo * RW + w];
                        phi[k] = g_mat[(size_t)rhi * RW + w];
                    }
                }
            }

            if (wid == 0) {
                unsigned valid0 = (lim >= 32) ? 0xFFFFFFFFu : ((1u << lim) - 1u);
                unsigned valid1 = (lim >= 64) ? 0xFFFFFFFFu
                                 : (lim > 32) ? ((1u << (lim - 32)) - 1u) : 0u;
                unsigned avail0 = valid0 & ~s_removed[2 * c];
                unsigned avail1 = valid1 & ~s_removed[2 * c + 1];
                unsigned kmlo = 0, kmhi = 0;
                int cnt = s_cnt;

                #pragma unroll
                for (int i = 0; i < 32; ++i) {
                    unsigned rl = __shfl_sync(0xffffffffu, d0lo, i);
                    unsigned rh = __shfl_sync(0xffffffffu, d0hi, i);
                    if (((avail0 >> i) & 1u) && cnt < MAX_DETS) {
                        kmlo |= 1u << i; ++cnt;
                        avail0 &= ~rl; avail1 &= ~rh;
                    }
                }
                #pragma unroll
                for (int i = 0; i < 32; ++i) {
                    unsigned rh = __shfl_sync(0xffffffffu, d1hi, i);
                    if (((avail1 >> i) & 1u) && cnt < MAX_DETS) {
                        kmhi |= 1u << i; ++cnt;
                        avail1 &= ~rh;
                    }
                }
                if (lane == 0) {
                    s_keepw[2 * c] = kmlo;
                    if (2 * c + 1 < Mw) s_keepw[2 * c + 1] = kmhi;
                    s_kmlo = kmlo; s_kmhi = kmhi; s_cnt = cnt;
                }
                // prefetch next chunk's diag (latency hidden by cross phase + barrier)
                d0lo = d0hi = d1hi = 0;
                if (c + 1 < Mc) {
                    int nb = (c + 1) * 64;
                    int r0 = nb + lane, r1 = nb + 32 + lane;
                    int w0 = 2 * c + 2, w1 = 2 * c + 3;
                    if (r0 < M) { d0lo = g_mat[(size_t)r0 * RW + w0];
                                  if (w1 < Mw) d0hi = g_mat[(size_t)r0 * RW + w1]; }
                    if (r1 < M && w1 < Mw) d1hi = g_mat[(size_t)r1 * RW + w1];
                }
            }
            __syncthreads();

            const unsigned kmlo = s_kmlo, kmhi = s_kmhi;
            const int stop = (s_cnt >= MAX_DETS);      // read strictly between the two barriers
            if (kmlo | kmhi) {
                const unsigned mlo = ((kmlo >> lane) & 1u) ? 0xFFFFFFFFu : 0u;
                const unsigned mhi = ((kmhi >> lane) & 1u) ? 0xFFFFFFFFu : 0u;
                #pragma unroll
                for (int k = 0; k < XK; ++k) {
                    int w = 2 * c + 2 + wid + 16 * k;
                    unsigned v = (plo[k] & mlo) | (phi[k] & mhi);
                    unsigned red = __reduce_or_sync(0xffffffffu, v);
                    if (lane == 0 && red && w < Mw) s_removed[w] |= red;
                }
            }
            __syncthreads();
            if (stop) break;                           // uniform; later s_keepw words stay 0
        }
    }

    // ---- valid flags on ORIGINAL indices ----
    const float sy = img_info[4];    // image_info[2][0]
    const float sx = img_info[5];    // image_info[2][1]
    for (int t = tid; t < M; t += NTHR) {
        if ((s_keepw[t >> 5] >> (t & 31)) & 1u) {
            int orig = g_sortedIdx[t];
            float4 rb = ((const float4*)roi_boxes)[orig];
            bool allz = (rb.x == 0.f && rb.y == 0.f && rb.z == 0.f && rb.w == 0.f);
            float4 db = g_sortedBox[t];
            float area = (db.z / sy - db.x / sy) * (db.w / sx - db.y / sx);
            if (!allz && area > MIN_AREA)
                atomicOr(&s_flags[orig >> 5], 1u << (orig & 31));
        }
    }
    __syncthreads();

    // ---- inclusive prefix scan over 512 popcounts (warp shuffles) ----
    {
        int v = __popc(s_flags[tid]);
        #pragma unroll
        for (int off = 1; off < 32; off <<= 1) {
            int n = __shfl_up_sync(0xffffffff, v, off);
            if (lane >= off) v += n;
        }
        if (lane == 31) s_wsum[wid] = v;
        __syncthreads();
        if (wid == 0 && lane < 16) {
            int w = s_wsum[lane];
            #pragma unroll
            for (int off = 1; off < 16; off <<= 1) {
                int n = __shfl_up_sync(0x0000ffff, w, off);
                if (lane >= off) w += n;
            }
            s_wsum[lane] = w;
        }
        __syncthreads();
        int basew = (wid > 0) ? s_wsum[wid - 1] : 0;
        s_scan[tid] = basew + v;                         // inclusive
        if (tid == 0) s_count = s_wsum[15];
    }
    if (tid < KSEL) s_selidx[tid] = 0;                   // jnp.nonzero fill_value = 0
    __syncthreads();
    {
        int excl = s_scan[tid] - __popc(s_flags[tid]);
        if (excl < KSEL) {
            unsigned f = s_flags[tid];
            int r = excl;
            while (f && r < KSEL) {
                int b = __ffs(f) - 1; f &= f - 1;
                s_selidx[r] = tid * 32 + b;
                ++r;
            }
        }
    }
    __syncthreads();

    // ---- GEMM: S[25][65] = vis[idx] @ txt^T  (warp-per-2-rows, K split across lanes) ----
    if (wid < 13) {
        const int r0 = 2 * wid;
        const int r1 = r0 + 1;
        const bool has1 = (r1 < KSEL);
        const float4* v0 = (const float4*)(vis + (size_t)s_selidx[r0] * FEAT);
        const float4* v1 = (const float4*)(vis + (size_t)s_selidx[has1 ? r1 : r0] * FEAT);
        float4 a0[4], a1[4];
        #pragma unroll
        for (int q = 0; q < 4; ++q) {
            a0[q] = v0[q * 32 + lane];                   // coalesced: 32 lanes = 512B
            a1[q] = v1[q * 32 + lane];
        }
        for (int cc = 0; cc < NUM_CATS; ++cc) {
            const float4* tf = (const float4*)(txt + (size_t)cc * FEAT);
            float p0 = 0.f, p1 = 0.f;
            #pragma unroll
            for (int q = 0; q < 4; ++q) {
                float4 b = tf[q * 32 + lane];            // coalesced
                p0 += a0[q].x * b.x + a0[q].y * b.y + a0[q].z * b.z + a0[q].w * b.w;
                p1 += a1[q].x * b.x + a1[q].y * b.y + a1[q].z * b.z + a1[q].w * b.w;
            }
            #pragma unroll
            for (int off = 16; off; off >>= 1) {
                p0 += __shfl_xor_sync(0xffffffff, p0, off);
                p1 += __shfl_xor_sync(0xffffffff, p1, off);
            }
            if (lane == 0) {
                S[r0][cc] = p0;
                if (has1) S[r1][cc] = p1;
            }
        }
    }
    __syncthreads();

    // ---- per-row max / argmax, fg, sort key ----
    if (tid < KSEL) {
        float mx = S[tid][0]; int am = 0;
        for (int cc = 1; cc < NUM_CATS; ++cc) {
            float v = S[tid][cc];
            if (v > mx) { mx = v; am = cc; }
        }
        bool rv = tid < min(s_count, KSEL);
        bool fg = rv && (am != 0);
        s_fgv[tid] = fg ? 1 : 0;
        s_key[tid] = fg ? mx : __int_as_float(0xff800000);   // -inf
    }
    __syncthreads();

    // ---- stable descending argsort via rank ----
    if (tid < KSEL) {
        float k = s_key[tid];
        int rank = 0;
        for (int j = 0; j < KSEL; ++j) {
            float kj = s_key[j];
            if (kj > k || (kj == k && j < tid)) ++rank;
        }
        s_src[rank] = tid;
    }
    __syncthreads();

    // ---- outputs: scores (25x64) | bboxes (25x4) | mask (25) ----
    for (int p = tid; p < KSEL * (NUM_CATS - 1); p += NTHR) {
        int row = p / (NUM_CATS - 1), cc = p - row * (NUM_CATS - 1);
        int s = s_src[row];
        out[p] = s_fgv[s] ? S[s][cc + 1] : 0.f;
    }
    if (tid < KSEL) {
        int s = s_src[tid];
        bool m = s_fgv[s] != 0;
        float4 db = ((const float4*)det_boxes)[s_selidx[s]];
        float xmin = db.y / sx, ymin = db.x / sy, xmax = db.w / sx, ymax = db.z / sy;
        float* o = out + KSEL * (NUM_CATS - 1) + tid * 4;
        o[0] = m ? xmin : 0.f;
        o[1] = m ? ymin : 0.f;
        o[2] = m ? xmax : 0.f;
        o[3] = m ? ymax : 0.f;
        out[KSEL * (NUM_CATS - 1) + KSEL * 4 + tid] = m ? 1.f : 0.f;
    }
}

// ---------------- launch ----------------
extern "C" void kernel_launch(void* const* d_in, const int* in_sizes, int n_in,
                              void* d_out, int out_size) {
    const float* roi_boxes  = (const float*)d_in[0];
    const float* roi_scores = (const float*)d_in[1];
    const float* det_boxes  = (const float*)d_in[2];
    /* d_in[3]: detection_masks — unused by reference outputs */
    const float* vis        = (const float*)d_in[4];
    const float* img_info   = (const float*)d_in[5];
    const float* txt        = (const float*)d_in[6];
    float* out = (float*)d_out;

    kPrep<<<1, 1024>>>(roi_scores, det_boxes);
    kMatrix<<<512, 256>>>();
    kFinal<<<1, NTHR>>>(roi_boxes, det_boxes, vis, img_info, txt, out);
}

// round 12
// speedup vs baseline: 1.0512x; 1.0512x over previous
#include <cuda_runtime.h>
#include <cstdint>

#define N_BOX 16384
#define FEAT 512
#define NUM_CATS 65
#define KSEL 25
#define MAX_DETS 1000
#define NMS_THRESH 0.6f
#define MIN_RPN 0.9f
#define MIN_AREA 220.0f
#define FLAG_WORDS 512      /* 16384/32 */
#define CAP 4096            /* hard cap on boxes passing score gate */
#define RW  (CAP / 32)      /* 128 words per matrix row */

#define NBUCK 4096
#define BUCK_SHIFT 9
#define BUCK_BASE 0x3F666666u   /* bits of 0.9f; scores in [0.9,1) share one exponent */

// ---------------- device scratch ----------------
__device__ int    g_M;
__device__ int    g_sortedIdx[CAP];
__device__ float4 g_sortedBox[CAP];
__device__ float  g_areaArr[CAP];
__device__ unsigned long long g_keys[CAP];     // sort keys (global: keeps kPrep smem < 48KB)
__device__ unsigned g_mat[(size_t)CAP * RW];   // suppression bitmask, words w >= i>>5 (bits j>i)

typedef unsigned long long u64;

// ================= kernel 1: compact + counting sort + gather =================
__global__ __launch_bounds__(1024, 1)
void kPrep(const float* __restrict__ roi_scores,
           const float* __restrict__ det_boxes) {
    __shared__ int sBase[NBUCK];               // 16 KB
    __shared__ int sCur[NBUCK];                // 16 KB (count, then cursor)
    __shared__ int s_wsum[32];
    __shared__ int s_M;

    const int tid  = threadIdx.x;
    const int lane = tid & 31;
    const int wid  = tid >> 5;                 // 32 warps

    #pragma unroll
    for (int k = 0; k < 4; ++k) sCur[tid * 4 + k] = 0;
    __syncthreads();

    // ---- phase 1: histogram of passing scores ----
    #pragma unroll
    for (int it = 0; it < N_BOX / 1024; ++it) {
        int i = tid + it * 1024;
        float s = roi_scores[i];
        if (s >= MIN_RPN) {
            unsigned bits = __float_as_uint(s);
            int b = min((int)((bits - BUCK_BASE) >> BUCK_SHIFT), NBUCK - 1);
            atomicAdd(&sCur[b], 1);
        }
    }
    __syncthreads();

    // ---- phase 2: exclusive scan in DESCENDING bucket order ----
    {
        int c[4], sum = 0;
        #pragma unroll
        for (int k = 0; k < 4; ++k) {
            int b = NBUCK - 1 - (tid * 4 + k);
            c[k] = sCur[b];
            sum += c[k];
        }
        int v = sum;
        #pragma unroll
        for (int off = 1; off < 32; off <<= 1) {
            int n = __shfl_up_sync(0xffffffffu, v, off);
            if (lane >= off) v += n;
        }
        if (lane == 31) s_wsum[wid] = v;
        __syncthreads();
        if (wid == 0) {
            int w = s_wsum[lane];
            #pragma unroll
            for (int off = 1; off < 32; off <<= 1) {
                int n = __shfl_up_sync(0xffffffffu, w, off);
                if (lane >= off) w += n;
            }
            s_wsum[lane] = w;
        }
        __syncthreads();
        int base = ((wid > 0) ? s_wsum[wid - 1] : 0) + (v - sum);  // exclusive for this thread
        #pragma unroll
        for (int k = 0; k < 4; ++k) {
            int b = NBUCK - 1 - (tid * 4 + k);
            sBase[b] = base;
            base += c[k];
        }
        if (tid == 0) s_M = min(s_wsum[31], CAP);
    }
    __syncthreads();
    const int M = s_M;
    if (tid == 0) g_M = M;
    #pragma unroll
    for (int k = 0; k < 4; ++k) {
        int b = tid * 4 + k;
        sCur[b] = sBase[b];                    // cursor = base
    }
    __syncthreads();

    // ---- phase 3: scatter keys to (nearly) sorted positions ----
    #pragma unroll
    for (int it = 0; it < N_BOX / 1024; ++it) {
        int i = tid + it * 1024;
        float s = roi_scores[i];
        if (s >= MIN_RPN) {
            unsigned bits = __float_as_uint(s);
            int b = min((int)((bits - BUCK_BASE) >> BUCK_SHIFT), NBUCK - 1);
            int pos = atomicAdd(&sCur[b], 1);
            if (pos < CAP)
                g_keys[pos] = ((u64)(0xFFFFFFFFu - bits) << 32) | (unsigned)i;
        }
    }
    __syncthreads();   // also fences block-visible global writes

    // ---- phase 4: fixup multi-occupancy buckets (exact (score desc, idx asc) order) ----
    #pragma unroll
    for (int k = 0; k < 4; ++k) {
        int b = tid * 4 + k;
        int st = sBase[b];
        int en = (b > 0) ? sBase[b - 1] : M;   // descending layout: next-lower bucket's base
        if (en > CAP) en = CAP;
        if (en - st > 1) {
            for (int a = st + 1; a < en; ++a) { // insertion sort (ascending keys)
                u64 key = g_keys[a];
                int p = a - 1;
                while (p >= st && g_keys[p] > key) { g_keys[p + 1] = g_keys[p]; --p; }
                g_keys[p + 1] = key;
            }
        }
    }
    __syncthreads();

    // ---- phase 5: gather boxes in sorted order ----
    for (int t = tid; t < M; t += 1024) {
        u64 key = g_keys[t];
        int orig = (int)(key & 0xFFFFFFFFu);
        g_sortedIdx[t] = orig;
        float4 b = ((const float4*)det_boxes)[orig];   // [y1, x1, y2, x2]
        g_sortedBox[t] = b;
        g_areaArr[t] = (b.w - b.y) * (b.z - b.x);      // (x2-x1)*(y2-y1)
    }
}

// ================= kernel 2: warp-tiled suppression bitmask =================
// One warp per 32x32 tile (row-word iw, col-word w >= iw). Lane = row; col boxes
// broadcast via shfl. 4 LDG per lane per tile instead of 64 (LSU floor was the
// previous kernel's bottleneck). Per-pair math bit-identical to the reference.
__global__ void kMatrixW() {
    const int M  = g_M;
    const int Mw = (M + 31) >> 5;
    const int nT = Mw * Mw;
    const int lane = threadIdx.x & 31;
    const int gw = (blockIdx.x * blockDim.x + threadIdx.x) >> 5;
    const int nW = (gridDim.x * blockDim.x) >> 5;

    for (int t = gw; t < nT; t += nW) {
        int iw = t / Mw;
        int w  = t - iw * Mw;
        if (w < iw) continue;                    // triangle only

        int i = iw * 32 + lane;                  // this lane's row
        int jl = w * 32 + lane;                  // this lane's col (held for broadcast)
        float4 bi = g_sortedBox[min(i,  M - 1)];
        float  ai = g_areaArr [min(i,  M - 1)];
        float4 cb = g_sortedBox[min(jl, M - 1)];
        float  ca = g_areaArr [min(jl, M - 1)];

        unsigned bits = 0;
        #pragma unroll
        for (int jj = 0; jj < 32; ++jj) {
            float by1 = __shfl_sync(0xffffffffu, cb.x, jj);
            float bx1 = __shfl_sync(0xffffffffu, cb.y, jj);
            float by2 = __shfl_sync(0xffffffffu, cb.z, jj);
            float bx2 = __shfl_sync(0xffffffffu, cb.w, jj);
            float aj  = __shfl_sync(0xffffffffu, ca,   jj);
            int jc = w * 32 + jj;
            // raw extents: clamped inter > 0 <=> both > 0; products then bit-identical
            float iw_ = fminf(bi.w, bx2) - fmaxf(bi.y, bx1);
            float ih_ = fminf(bi.z, by2) - fmaxf(bi.x, by1);
            bool ok = (iw_ > 0.0f) && (ih_ > 0.0f) && (jc > i) && (jc < M);
            if (ok) {
                float inter = iw_ * ih_;
                float iou = inter / (ai + aj - inter + 1e-12f);
                ok = iou > NMS_THRESH;
            }
            bits |= (ok ? 1u : 0u) << jj;
        }
        if (i < M) g_mat[(size_t)i * RW + w] = bits;
    }
}

// ================= kernel 3: 64-box-chunk scan + select + GEMM + sort + outputs =================
#define NTHR 512

__global__ __launch_bounds__(NTHR, 1)
void kFinal(const float* __restrict__ roi_boxes,
            const float* __restrict__ det_boxes,
            const float* __restrict__ vis,
            const float* __restrict__ img_info,
            const float* __restrict__ txt,
            float* __restrict__ out) {
    __shared__ unsigned s_removed[RW];
    __shared__ unsigned s_keepw[RW];
    __shared__ unsigned s_flags[FLAG_WORDS];
    __shared__ int      s_scan[FLAG_WORDS];
    __shared__ int      s_wsum[16];
    __shared__ unsigned s_kmlo, s_kmhi;
    __shared__ int      s_cnt;
    __shared__ int      s_count;
    __shared__ int      s_selidx[KSEL];
    __shared__ float    S[KSEL][NUM_CATS];
    __shared__ float    s_key[KSEL];
    __shared__ int      s_src[KSEL];
    __shared__ unsigned char s_fgv[KSEL];

    const int tid  = threadIdx.x;
    const int lane = tid & 31;
    const int wid  = tid >> 5;          // 16 warps
    const int M    = g_M;
    const int Mw   = (M + 31) >> 5;
    const int Mc   = (M + 63) >> 6;     // 64-box chunks

    for (int t = tid; t < RW; t += NTHR) { s_removed[t] = 0; s_keepw[t] = 0; }
    for (int t = tid; t < FLAG_WORDS; t += NTHR) s_flags[t] = 0;
    if (tid == 0) s_cnt = 0;
    __syncthreads();

    // ---- chunked greedy NMS scan: warp0 resolves 64 boxes in registers, 16 warps propagate ----
    {
        // warp0's diag registers for current chunk (lane holds its own rows' words)
        unsigned d0lo = 0, d0hi = 0, d1hi = 0;
        if (wid == 0 && Mc > 0) {
            int r0 = lane, r1 = 32 + lane;
            if (r0 < M) { d0lo = g_mat[(size_t)r0 * RW + 0];
                          if (1 < Mw) d0hi = g_mat[(size_t)r0 * RW + 1]; }
            if (r1 < M && 1 < Mw) d1hi = g_mat[(size_t)r1 * RW + 1];
        }

        for (int c = 0; c < Mc; ++c) {
            const int base = c * 64;
            const int lim  = M - base;                 // >0

            if (wid == 0) {
                unsigned valid0 = (lim >= 32) ? 0xFFFFFFFFu : ((1u << lim) - 1u);
                unsigned valid1 = (lim >= 64) ? 0xFFFFFFFFu
                                 : (lim > 32) ? ((1u << (lim - 32)) - 1u) : 0u;
                unsigned avail0 = valid0 & ~s_removed[2 * c];
                unsigned avail1 = valid1 & ~s_removed[2 * c + 1];
                unsigned kmlo = 0, kmhi = 0;
                int cnt = s_cnt;

                #pragma unroll
                for (int i = 0; i < 32; ++i) {
                    unsigned rlo = __shfl_sync(0xffffffffu, d0lo, i);
                    unsigned rhi = __shfl_sync(0xffffffffu, d0hi, i);
                    if (((avail0 >> i) & 1u) && cnt < MAX_DETS) {
                        kmlo |= 1u << i; ++cnt;
                        avail0 &= ~rlo; avail1 &= ~rhi;
                    }
                }
                #pragma unroll
                for (int i = 0; i < 32; ++i) {
                    unsigned rhi = __shfl_sync(0xffffffffu, d1hi, i);
                    if (((avail1 >> i) & 1u) && cnt < MAX_DETS) {
                        kmhi |= 1u << i; ++cnt;
                        avail1 &= ~rhi;
                    }
                }
                if (lane == 0) {
                    s_keepw[2 * c] = kmlo;
                    if (2 * c + 1 < Mw) s_keepw[2 * c + 1] = kmhi;
                    s_kmlo = kmlo; s_kmhi = kmhi; s_cnt = cnt;
                }
                // prefetch next chunk's diag (latency hidden by cross phase + barrier)
                d0lo = d0hi = d1hi = 0;
                if (c + 1 < Mc) {
                    int nb = (c + 1) * 64;
                    int r0 = nb + lane, r1 = nb + 32 + lane;
                    int w0 = 2 * c + 2, w1 = 2 * c + 3;
                    if (r0 < M) { d0lo = g_mat[(size_t)r0 * RW + w0];
                                  if (w1 < Mw) d0hi = g_mat[(size_t)r0 * RW + w1]; }
                    if (r1 < M && w1 < Mw) d1hi = g_mat[(size_t)r1 * RW + w1];
                }
            }
            __syncthreads();

            const unsigned kmlo = s_kmlo, kmhi = s_kmhi;
            const int stop = (s_cnt >= MAX_DETS);      // read strictly between the two barriers
            if (kmlo | kmhi) {
                for (int w = 2 * c + 2 + wid; w < Mw; w += 16) {
                    unsigned v = 0;
                    if ((kmlo >> lane) & 1u) v |= g_mat[(size_t)(base + lane) * RW + w];
                    if ((kmhi >> lane) & 1u) v |= g_mat[(size_t)(base + 32 + lane) * RW + w];
                    unsigned red = __reduce_or_sync(0xffffffffu, v);
                    if (lane == 0 && red) s_removed[w] |= red;
                }
            }
            __syncthreads();
            if (stop) break;                           // uniform; later s_keepw words stay 0
        }
    }

    // ---- valid flags on ORIGINAL indices ----
    const float sy = img_info[4];    // image_info[2][0]
    const float sx = img_info[5];    // image_info[2][1]
    for (int t = tid; t < M; t += NTHR) {
        if ((s_keepw[t >> 5] >> (t & 31)) & 1u) {
            int orig = g_sortedIdx[t];
            float4 rb = ((const float4*)roi_boxes)[orig];
            bool allz = (rb.x == 0.f && rb.y == 0.f && rb.z == 0.f && rb.w == 0.f);
            float4 db = g_sortedBox[t];
            float area = (db.z / sy - db.x / sy) * (db.w / sx - db.y / sx);
            if (!allz && area > MIN_AREA)
                atomicOr(&s_flags[orig >> 5], 1u << (orig & 31));
        }
    }
    __syncthreads();

    // ---- inclusive prefix scan over 512 popcounts (warp shuffles) ----
    {
        int v = __popc(s_flags[tid]);
        #pragma unroll
        for (int off = 1; off < 32; off <<= 1) {
            int n = __shfl_up_sync(0xffffffff, v, off);
            if (lane >= off) v += n;
        }
        if (lane == 31) s_wsum[wid] = v;
        __syncthreads();
        if (wid == 0 && lane < 16) {
            int w = s_wsum[lane];
            #pragma unroll
            for (int off = 1; off < 16; off <<= 1) {
                int n = __shfl_up_sync(0x0000ffff, w, off);
                if (lane >= off) w += n;
            }
            s_wsum[lane] = w;
        }
        __syncthreads();
        int basew = (wid > 0) ? s_wsum[wid - 1] : 0;
        s_scan[tid] = basew + v;                         // inclusive
        if (tid == 0) s_count = s_wsum[15];
    }
    if (tid < KSEL) s_selidx[tid] = 0;                   // jnp.nonzero fill_value = 0
    __syncthreads();
    {
        int excl = s_scan[tid] - __popc(s_flags[tid]);
        if (excl < KSEL) {
            unsigned f = s_flags[tid];
            int r = excl;
            while (f && r < KSEL) {
                int b = __ffs(f) - 1; f &= f - 1;
                s_selidx[r] = tid * 32 + b;
                ++r;
            }
        }
    }
    __syncthreads();

    // ---- GEMM: S[25][65] = vis[idx] @ txt^T  (warp-per-2-rows, K split across lanes) ----
    if (wid < 13) {
        const int r0 = 2 * wid;
        const int r1 = r0 + 1;
        const bool has1 = (r1 < KSEL);
        const float4* v0 = (const float4*)(vis + (size_t)s_selidx[r0] * FEAT);
        const float4* v1 = (const float4*)(vis + (size_t)s_selidx[has1 ? r1 : r0] * FEAT);
        float4 a0[4], a1[4];
        #pragma unroll
        for (int q = 0; q < 4; ++q) {
            a0[q] = v0[q * 32 + lane];                   // coalesced: 32 lanes = 512B
            a1[q] = v1[q * 32 + lane];
        }
        for (int cc = 0; cc < NUM_CATS; ++cc) {
            const float4* tf = (const float4*)(txt + (size_t)cc * FEAT);
            float p0 = 0.f, p1 = 0.f;
            #pragma unroll
            for (int q = 0; q < 4; ++q) {
                float4 b = tf[q * 32 + lane];            // coalesced
                p0 += a0[q].x * b.x + a0[q].y * b.y + a0[q].z * b.z + a0[q].w * b.w;
                p1 += a1[q].x * b.x + a1[q].y * b.y + a1[q].z * b.z + a1[q].w * b.w;
            }
            #pragma unroll
            for (int off = 16; off; off >>= 1) {
                p0 += __shfl_xor_sync(0xffffffff, p0, off);
                p1 += __shfl_xor_sync(0xffffffff, p1, off);
            }
            if (lane == 0) {
                S[r0][cc] = p0;
                if (has1) S[r1][cc] = p1;
            }
        }
    }
    __syncthreads();

    // ---- per-row max / argmax, fg, sort key ----
    if (tid < KSEL) {
        float mx = S[tid][0]; int am = 0;
        for (int cc = 1; cc < NUM_CATS; ++cc) {
            float v = S[tid][cc];
            if (v > mx) { mx = v; am = cc; }
        }
        bool rv = tid < min(s_count, KSEL);
        bool fg = rv && (am != 0);
        s_fgv[tid] = fg ? 1 : 0;
        s_key[tid] = fg ? mx : __int_as_float(0xff800000);   // -inf
    }
    __syncthreads();

    // ---- stable descending argsort via rank ----
    if (tid < KSEL) {
        float k = s_key[tid];
        int rank = 0;
        for (int j = 0; j < KSEL; ++j) {
            float kj = s_key[j];
            if (kj > k || (kj == k && j < tid)) ++rank;
        }
        s_src[rank] = tid;
    }
    __syncthreads();

    // ---- outputs: scores (25x64) | bboxes (25x4) | mask (25) ----
    for (int p = tid; p < KSEL * (NUM_CATS - 1); p += NTHR) {
        int row = p / (NUM_CATS - 1), cc = p - row * (NUM_CATS - 1);
        int s = s_src[row];
        out[p] = s_fgv[s] ? S[s][cc + 1] : 0.f;
    }
    if (tid < KSEL) {
        int s = s_src[tid];
        bool m = s_fgv[s] != 0;
        float4 db = ((const float4*)det_boxes)[s_selidx[s]];
        float xmin = db.y / sx, ymin = db.x / sy, xmax = db.w / sx, ymax = db.z / sy;
        float* o = out + KSEL * (NUM_CATS - 1) + tid * 4;
        o[0] = m ? xmin : 0.f;
        o[1] = m ? ymin : 0.f;
        o[2] = m ? xmax : 0.f;
        o[3] = m ? ymax : 0.f;
        out[KSEL * (NUM_CATS - 1) + KSEL * 4 + tid] = m ? 1.f : 0.f;
    }
}

// ---------------- launch ----------------
extern "C" void kernel_launch(void* const* d_in, const int* in_sizes, int n_in,
                              void* d_out, int out_size) {
    const float* roi_boxes  = (const float*)d_in[0];
    const float* roi_scores = (const float*)d_in[1];
    const float* det_boxes  = (const float*)d_in[2];
    /* d_in[3]: detection_masks — unused by reference outputs */
    const float* vis        = (const float*)d_in[4];
    const float* img_info   = (const float*)d_in[5];
    const float* txt        = (const float*)d_in[6];
    float* out = (float*)d_out;

    kPrep<<<1, 1024>>>(roi_scores, det_boxes);
    kMatrixW<<<352, 256>>>();
    kFinal<<<1, NTHR>>>(roi_boxes, det_boxes, vis, img_info, txt, out);
}

// round 14
// speedup vs baseline: 1.1985x; 1.1400x over previous
#include <cuda_runtime.h>
#include <cstdint>

#define N_BOX 16384
#define FEAT 512
#define NUM_CATS 65
#define KSEL 25
#define MAX_DETS 1000
#define NMS_THRESH 0.6f
#define MIN_RPN 0.9f
#define MIN_AREA 220.0f
#define FLAG_WORDS 512      /* 16384/32 */
#define CAP 4096            /* hard cap on boxes passing score gate */
#define RW  (CAP / 32)      /* 128 words per matrix row */

#define NBUCK 4096
#define BUCK_SHIFT 9
#define BUCK_BASE 0x3F666666u   /* bits of 0.9f; scores in [0.9,1) share one exponent */

// ---------------- device scratch ----------------
__device__ int    g_M;
__device__ int    g_sortedIdx[CAP];
__device__ float4 g_sortedBox[CAP];
__device__ float  g_areaArr[CAP];
// TRANSPOSED suppression bitmask: g_matT[(size_t)w * CAP + i] holds word w of row i
// (bits j = w*32+jj, restricted to j > i). Consecutive rows i are contiguous ->
// every kFinal read and kMatrixW write is coalesced.
__device__ unsigned g_matT[(size_t)RW * CAP];

typedef unsigned long long u64;

// ================= kernel 1: compact + counting sort (keys in smem) + gather =================
__global__ __launch_bounds__(1024, 1)
void kPrep(const float* __restrict__ roi_scores,
           const float* __restrict__ det_boxes) {
    extern __shared__ u64 sKeys[];             // CAP entries = 32 KB (dynamic, opt-in)
    __shared__ int sBase[NBUCK];               // 16 KB
    __shared__ int sCur[NBUCK];                // 16 KB (count, then cursor)
    __shared__ int s_wsum[32];
    __shared__ int s_M;

    const int tid  = threadIdx.x;
    const int lane = tid & 31;
    const int wid  = tid >> 5;                 // 32 warps

    #pragma unroll
    for (int k = 0; k < 4; ++k) sCur[tid * 4 + k] = 0;
    __syncthreads();

    // ---- phase 1: histogram of passing scores ----
    #pragma unroll
    for (int it = 0; it < N_BOX / 1024; ++it) {
        int i = tid + it * 1024;
        float s = roi_scores[i];
        if (s >= MIN_RPN) {
            unsigned bits = __float_as_uint(s);
            int b = min((int)((bits - BUCK_BASE) >> BUCK_SHIFT), NBUCK - 1);
            atomicAdd(&sCur[b], 1);
        }
    }
    __syncthreads();

    // ---- phase 2: exclusive scan in DESCENDING bucket order ----
    {
        int c[4], sum = 0;
        #pragma unroll
        for (int k = 0; k < 4; ++k) {
            int b = NBUCK - 1 - (tid * 4 + k);
            c[k] = sCur[b];
            sum += c[k];
        }
        int v = sum;
        #pragma unroll
        for (int off = 1; off < 32; off <<= 1) {
            int n = __shfl_up_sync(0xffffffffu, v, off);
            if (lane >= off) v += n;
        }
        if (lane == 31) s_wsum[wid] = v;
        __syncthreads();
        if (wid == 0) {
            int w = s_wsum[lane];
            #pragma unroll
            for (int off = 1; off < 32; off <<= 1) {
                int n = __shfl_up_sync(0xffffffffu, w, off);
                if (lane >= off) w += n;
            }
            s_wsum[lane] = w;
        }
        __syncthreads();
        int base = ((wid > 0) ? s_wsum[wid - 1] : 0) + (v - sum);  // exclusive for this thread
        #pragma unroll
        for (int k = 0; k < 4; ++k) {
            int b = NBUCK - 1 - (tid * 4 + k);
            sBase[b] = base;
            base += c[k];
        }
        if (tid == 0) s_M = min(s_wsum[31], CAP);
    }
    __syncthreads();
    const int M = s_M;
    if (tid == 0) g_M = M;
    #pragma unroll
    for (int k = 0; k < 4; ++k) {
        int b = tid * 4 + k;
        sCur[b] = sBase[b];                    // cursor = base
    }
    __syncthreads();

    // ---- phase 3: scatter keys to (nearly) sorted positions (smem) ----
    #pragma unroll
    for (int it = 0; it < N_BOX / 1024; ++it) {
        int i = tid + it * 1024;
        float s = roi_scores[i];
        if (s >= MIN_RPN) {
            unsigned bits = __float_as_uint(s);
            int b = min((int)((bits - BUCK_BASE) >> BUCK_SHIFT), NBUCK - 1);
            int pos = atomicAdd(&sCur[b], 1);
            if (pos < CAP)
                sKeys[pos] = ((u64)(0xFFFFFFFFu - bits) << 32) | (unsigned)i;
        }
    }
    __syncthreads();

    // ---- phase 4: fixup multi-occupancy buckets (exact (score desc, idx asc) order) ----
    #pragma unroll
    for (int k = 0; k < 4; ++k) {
        int b = tid * 4 + k;
        int st = sBase[b];
        int en = (b > 0) ? sBase[b - 1] : M;   // descending layout: next-lower bucket's base
        if (en > CAP) en = CAP;
        if (en - st > 1) {
            for (int a = st + 1; a < en; ++a) { // insertion sort (ascending keys)
                u64 key = sKeys[a];
                int p = a - 1;
                while (p >= st && sKeys[p] > key) { sKeys[p + 1] = sKeys[p]; --p; }
                sKeys[p + 1] = key;
            }
        }
    }
    __syncthreads();

    // ---- phase 5: gather boxes in sorted order ----
    for (int t = tid; t < M; t += 1024) {
        u64 key = sKeys[t];
        int orig = (int)(key & 0xFFFFFFFFu);
        g_sortedIdx[t] = orig;
        float4 b = ((const float4*)det_boxes)[orig];   // [y1, x1, y2, x2]
        g_sortedBox[t] = b;
        g_areaArr[t] = (b.w - b.y) * (b.z - b.x);      // (x2-x1)*(y2-y1)
    }
}

// ================= kernel 2: warp-tiled suppression bitmask (transposed output) =================
// One warp per 32x32 tile (row-word iw, col-word w >= iw). Lane = row; col boxes
// broadcast via shfl. Output g_matT[w*CAP + i]: lanes write consecutive addresses.
__global__ void kMatrixW() {
    const int M  = g_M;
    const int Mw = (M + 31) >> 5;
    const int nT = Mw * Mw;
    const int lane = threadIdx.x & 31;
    const int gw = (blockIdx.x * blockDim.x + threadIdx.x) >> 5;
    const int nW = (gridDim.x * blockDim.x) >> 5;

    for (int t = gw; t < nT; t += nW) {
        int iw = t / Mw;
        int w  = t - iw * Mw;
        if (w < iw) continue;                    // triangle only

        int i = iw * 32 + lane;                  // this lane's row
        int jl = w * 32 + lane;                  // this lane's col (held for broadcast)
        float4 bi = g_sortedBox[min(i,  M - 1)];
        float  ai = g_areaArr [min(i,  M - 1)];
        float4 cb = g_sortedBox[min(jl, M - 1)];
        float  ca = g_areaArr [min(jl, M - 1)];

        unsigned bits = 0;
        #pragma unroll
        for (int jj = 0; jj < 32; ++jj) {
            float by1 = __shfl_sync(0xffffffffu, cb.x, jj);
            float bx1 = __shfl_sync(0xffffffffu, cb.y, jj);
            float by2 = __shfl_sync(0xffffffffu, cb.z, jj);
            float bx2 = __shfl_sync(0xffffffffu, cb.w, jj);
            float aj  = __shfl_sync(0xffffffffu, ca,   jj);
            int jc = w * 32 + jj;
            // raw extents: clamped inter > 0 <=> both > 0; products then bit-identical
            float iw_ = fminf(bi.w, bx2) - fmaxf(bi.y, bx1);
            float ih_ = fminf(bi.z, by2) - fmaxf(bi.x, by1);
            bool ok = (iw_ > 0.0f) && (ih_ > 0.0f) && (jc > i) && (jc < M);
            if (ok) {
                float inter = iw_ * ih_;
                float iou = inter / (ai + aj - inter + 1e-12f);
                ok = iou > NMS_THRESH;
            }
            bits |= (ok ? 1u : 0u) << jj;
        }
        if (i < M) g_matT[(size_t)w * CAP + i] = bits;   // coalesced store
    }
}

// ================= kernel 3: 64-box-chunk scan + select + GEMM + sort + outputs =================
#define NTHR 512

__global__ __launch_bounds__(NTHR, 1)
void kFinal(const float* __restrict__ roi_boxes,
            const float* __restrict__ det_boxes,
            const float* __restrict__ vis,
            const float* __restrict__ img_info,
            const float* __restrict__ txt,
            float* __restrict__ out) {
    __shared__ unsigned s_removed[RW];
    __shared__ unsigned s_keepw[RW];
    __shared__ unsigned s_flags[FLAG_WORDS];
    __shared__ int      s_scan[FLAG_WORDS];
    __shared__ int      s_wsum[16];
    __shared__ unsigned s_kmlo, s_kmhi;
    __shared__ int      s_cnt;
    __shared__ int      s_count;
    __shared__ int      s_selidx[KSEL];
    __shared__ float    S[KSEL][NUM_CATS];
    __shared__ float    s_key[KSEL];
    __shared__ int      s_src[KSEL];
    __shared__ unsigned char s_fgv[KSEL];

    const int tid  = threadIdx.x;
    const int lane = tid & 31;
    const int wid  = tid >> 5;          // 16 warps
    const int M    = g_M;
    const int Mw   = (M + 31) >> 5;
    const int Mc   = (M + 63) >> 6;     // 64-box chunks

    for (int t = tid; t < RW; t += NTHR) { s_removed[t] = 0; s_keepw[t] = 0; }
    for (int t = tid; t < FLAG_WORDS; t += NTHR) s_flags[t] = 0;
    if (tid == 0) s_cnt = 0;
    __syncthreads();

    // ---- chunked greedy NMS scan: warp0 resolves 64 boxes in registers, 16 warps propagate ----
    {
        // warp0's diag registers for current chunk (lane holds its own rows' words)
        unsigned d0lo = 0, d0hi = 0, d1hi = 0;
        if (wid == 0 && Mc > 0) {
            int r0 = lane, r1 = 32 + lane;
            if (r0 < M) { d0lo = g_matT[0 * CAP + r0];              // coalesced
                          if (1 < Mw) d0hi = g_matT[1 * CAP + r0]; }
            if (r1 < M && 1 < Mw) d1hi = g_matT[1 * CAP + r1];
        }

        for (int c = 0; c < Mc; ++c) {
            const int base = c * 64;
            const int lim  = M - base;                 // >0

            if (wid == 0) {
                unsigned valid0 = (lim >= 32) ? 0xFFFFFFFFu : ((1u << lim) - 1u);
                unsigned valid1 = (lim >= 64) ? 0xFFFFFFFFu
                                 : (lim > 32) ? ((1u << (lim - 32)) - 1u) : 0u;
                unsigned avail0 = valid0 & ~s_removed[2 * c];
                unsigned avail1 = valid1 & ~s_removed[2 * c + 1];
                unsigned kmlo = 0, kmhi = 0;
                int cnt = s_cnt;

                #pragma unroll
                for (int i = 0; i < 32; ++i) {
                    unsigned rlo = __shfl_sync(0xffffffffu, d0lo, i);
                    unsigned rhi = __shfl_sync(0xffffffffu, d0hi, i);
                    if (((avail0 >> i) & 1u) && cnt < MAX_DETS) {
                        kmlo |= 1u << i; ++cnt;
                        avail0 &= ~rlo; avail1 &= ~rhi;
                    }
                }
                #pragma unroll
                for (int i = 0; i < 32; ++i) {
                    unsigned rhi = __shfl_sync(0xffffffffu, d1hi, i);
                    if (((avail1 >> i) & 1u) && cnt < MAX_DETS) {
                        kmhi |= 1u << i; ++cnt;
                        avail1 &= ~rhi;
                    }
                }
                if (lane == 0) {
                    s_keepw[2 * c] = kmlo;
                    if (2 * c + 1 < Mw) s_keepw[2 * c + 1] = kmhi;
                    s_kmlo = kmlo; s_kmhi = kmhi; s_cnt = cnt;
                }
                // prefetch next chunk's diag (latency hidden by cross phase + barrier)
                d0lo = d0hi = d1hi = 0;
                if (c + 1 < Mc) {
                    int nb = (c + 1) * 64;
                    int r0 = nb + lane, r1 = nb + 32 + lane;
                    int w0 = 2 * c + 2, w1 = 2 * c + 3;
                    if (r0 < M) { d0lo = g_matT[(size_t)w0 * CAP + r0];
                                  if (w1 < Mw) d0hi = g_matT[(size_t)w1 * CAP + r0]; }
                    if (r1 < M && w1 < Mw) d1hi = g_matT[(size_t)w1 * CAP + r1];
                }
            }
            __syncthreads();

            const unsigned kmlo = s_kmlo, kmhi = s_kmhi;
            const int stop = (s_cnt >= MAX_DETS);      // read strictly between the two barriers
            if (kmlo | kmhi) {
                for (int w = 2 * c + 2 + wid; w < Mw; w += 16) {
                    unsigned v = 0;                     // coalesced: lanes = consecutive rows
                    if ((kmlo >> lane) & 1u) v |= g_matT[(size_t)w * CAP + base + lane];
                    if ((kmhi >> lane) & 1u) v |= g_matT[(size_t)w * CAP + base + 32 + lane];
                    unsigned red = __reduce_or_sync(0xffffffffu, v);
                    if (lane == 0 && red) s_removed[w] |= red;
                }
            }
            __syncthreads();
            if (stop) break;                           // uniform; later s_keepw words stay 0
        }
    }

    // ---- valid flags on ORIGINAL indices ----
    const float sy = img_info[4];    // image_info[2][0]
    const float sx = img_info[5];    // image_info[2][1]
    for (int t = tid; t < M; t += NTHR) {
        if ((s_keepw[t >> 5] >> (t & 31)) & 1u) {
            int orig = g_sortedIdx[t];
            float4 rb = ((const float4*)roi_boxes)[orig];
            bool allz = (rb.x == 0.f && rb.y == 0.f && rb.z == 0.f && rb.w == 0.f);
            float4 db = g_sortedBox[t];
            float area = (db.z / sy - db.x / sy) * (db.w / sx - db.y / sx);
            if (!allz && area > MIN_AREA)
                atomicOr(&s_flags[orig >> 5], 1u << (orig & 31));
        }
    }
    __syncthreads();

    // ---- inclusive prefix scan over 512 popcounts (warp shuffles) ----
    {
        int v = __popc(s_flags[tid]);
        #pragma unroll
        for (int off = 1; off < 32; off <<= 1) {
            int n = __shfl_up_sync(0xffffffff, v, off);
            if (lane >= off) v += n;
        }
        if (lane == 31) s_wsum[wid] = v;
        __syncthreads();
        if (wid == 0 && lane < 16) {
            int w = s_wsum[lane];
            #pragma unroll
            for (int off = 1; off < 16; off <<= 1) {
                int n = __shfl_up_sync(0x0000ffff, w, off);
                if (lane >= off) w += n;
            }
            s_wsum[lane] = w;
        }
        __syncthreads();
        int basew = (wid > 0) ? s_wsum[wid - 1] : 0;
        s_scan[tid] = basew + v;                         // inclusive
        if (tid == 0) s_count = s_wsum[15];
    }
    if (tid < KSEL) s_selidx[tid] = 0;                   // jnp.nonzero fill_value = 0
    __syncthreads();
    {
        int excl = s_scan[tid] - __popc(s_flags[tid]);
        if (excl < KSEL) {
            unsigned f = s_flags[tid];
            int r = excl;
            while (f && r < KSEL) {
                int b = __ffs(f) - 1; f &= f - 1;
                s_selidx[r] = tid * 32 + b;
                ++r;
            }
        }
    }
    __syncthreads();

    // ---- GEMM: S[25][65] = vis[idx] @ txt^T  (warp-per-2-rows, K split across lanes) ----
    if (wid < 13) {
        const int r0 = 2 * wid;
        const int r1 = r0 + 1;
        const bool has1 = (r1 < KSEL);
        const float4* v0 = (const float4*)(vis + (size_t)s_selidx[r0] * FEAT);
        const float4* v1 = (const float4*)(vis + (size_t)s_selidx[has1 ? r1 : r0] * FEAT);
        float4 a0[4], a1[4];
        #pragma unroll
        for (int q = 0; q < 4; ++q) {
            a0[q] = v0[q * 32 + lane];                   // coalesced: 32 lanes = 512B
            a1[q] = v1[q * 32 + lane];
        }
        for (int cc = 0; cc < NUM_CATS; ++cc) {
            const float4* tf = (const float4*)(txt + (size_t)cc * FEAT);
            float p0 = 0.f, p1 = 0.f;
            #pragma unroll
            for (int q = 0; q < 4; ++q) {
                float4 b = tf[q * 32 + lane];            // coalesced
                p0 += a0[q].x * b.x + a0[q].y * b.y + a0[q].z * b.z + a0[q].w * b.w;
                p1 += a1[q].x * b.x + a1[q].y * b.y + a1[q].z * b.z + a1[q].w * b.w;
            }
            #pragma unroll
            for (int off = 16; off; off >>= 1) {
                p0 += __shfl_xor_sync(0xffffffff, p0, off);
                p1 += __shfl_xor_sync(0xffffffff, p1, off);
            }
            if (lane == 0) {
                S[r0][cc] = p0;
                if (has1) S[r1][cc] = p1;
            }
        }
    }
    __syncthreads();

    // ---- per-row max / argmax, fg, sort key ----
    if (tid < KSEL) {
        float mx = S[tid][0]; int am = 0;
        for (int cc = 1; cc < NUM_CATS; ++cc) {
            float v = S[tid][cc];
            if (v > mx) { mx = v; am = cc; }
        }
        bool rv = tid < min(s_count, KSEL);
        bool fg = rv && (am != 0);
        s_fgv[tid] = fg ? 1 : 0;
        s_key[tid] = fg ? mx : __int_as_float(0xff800000);   // -inf
    }
    __syncthreads();

    // ---- stable descending argsort via rank ----
    if (tid < KSEL) {
        float k = s_key[tid];
        int rank = 0;
        for (int j = 0; j < KSEL; ++j) {
            float kj = s_key[j];
            if (kj > k || (kj == k && j < tid)) ++rank;
        }
        s_src[rank] = tid;
    }
    __syncthreads();

    // ---- outputs: scores (25x64) | bboxes (25x4) | mask (25) ----
    for (int p = tid; p < KSEL * (NUM_CATS - 1); p += NTHR) {
        int row = p / (NUM_CATS - 1), cc = p - row * (NUM_CATS - 1);
        int s = s_src[row];
        out[p] = s_fgv[s] ? S[s][cc + 1] : 0.f;
    }
    if (tid < KSEL) {
        int s = s_src[tid];
        bool m = s_fgv[s] != 0;
        float4 db = ((const float4*)det_boxes)[s_selidx[s]];
        float xmin = db.y / sx, ymin = db.x / sy, xmax = db.w / sx, ymax = db.z / sy;
        float* o = out + KSEL * (NUM_CATS - 1) + tid * 4;
        o[0] = m ? xmin : 0.f;
        o[1] = m ? ymin : 0.f;
        o[2] = m ? xmax : 0.f;
        o[3] = m ? ymax : 0.f;
        out[KSEL * (NUM_CATS - 1) + KSEL * 4 + tid] = m ? 1.f : 0.f;
    }
}

// ---------------- launch ----------------
extern "C" void kernel_launch(void* const* d_in, const int* in_sizes, int n_in,
                              void* d_out, int out_size) {
    const float* roi_boxes  = (const float*)d_in[0];
    const float* roi_scores = (const float*)d_in[1];
    const float* det_boxes  = (const float*)d_in[2];
    /* d_in[3]: detection_masks — unused by reference outputs */
    const float* vis        = (const float*)d_in[4];
    const float* img_info   = (const float*)d_in[5];
    const float* txt        = (const float*)d_in[6];
    float* out = (float*)d_out;

    static int attr_done = 0;
    if (!attr_done) {
        cudaFuncSetAttribute(kPrep, cudaFuncAttributeMaxDynamicSharedMemorySize, CAP * 8);
        attr_done = 1;
    }
    kPrep<<<1, 1024, CAP * 8>>>(roi_scores, det_boxes);
    kMatrixW<<<352, 256>>>();
    kFinal<<<1, NTHR>>>(roi_boxes, det_boxes, vis, img_info, txt, out);
}

// round 15
// speedup vs baseline: 1.3493x; 1.1259x over previous
#include <cuda_runtime.h>
#include <cstdint>

#define N_BOX 16384
#define FEAT 512
#define NUM_CATS 65
#define KSEL 25
#define MAX_DETS 1000
#define NMS_THRESH 0.6f
#define MIN_RPN 0.9f
#define MIN_AREA 220.0f
#define FLAG_WORDS 512      /* 16384/32 */
#define CAP 4096            /* hard cap on boxes passing score gate */
#define RW  (CAP / 32)      /* 128 words per matrix row */

#define NBUCK 4096
#define BUCK_SHIFT 9
#define BUCK_BASE 0x3F666666u   /* bits of 0.9f; scores in [0.9,1) share one exponent */

// ---------------- device scratch ----------------
__device__ int    g_M;
__device__ int    g_sortedIdx[CAP];
__device__ float4 g_sortedBox[CAP];
__device__ float  g_areaArr[CAP];
// TRANSPOSED suppression bitmask: g_matT[(size_t)w * CAP + i] holds word w of row i
// (bits j = w*32+jj, restricted to j > i). Consecutive rows i are contiguous ->
// every kFinal read and kMatrixW write is coalesced.
__device__ unsigned g_matT[(size_t)RW * CAP];

typedef unsigned long long u64;

// ================= kernel 1: compact + counting sort (keys in smem) + gather =================
__global__ __launch_bounds__(1024, 1)
void kPrep(const float* __restrict__ roi_scores,
           const float* __restrict__ det_boxes) {
    extern __shared__ u64 sKeys[];             // CAP entries = 32 KB (dynamic, opt-in)
    __shared__ int sBase[NBUCK];               // 16 KB
    __shared__ int sCur[NBUCK];                // 16 KB (count, then cursor)
    __shared__ int s_wsum[32];
    __shared__ int s_M;

    const int tid  = threadIdx.x;
    const int lane = tid & 31;
    const int wid  = tid >> 5;                 // 32 warps

    #pragma unroll
    for (int k = 0; k < 4; ++k) sCur[tid * 4 + k] = 0;
    __syncthreads();

    // ---- phase 1: single global pass; keep passing-score bits in registers ----
    unsigned sb[16];
    #pragma unroll
    for (int it = 0; it < 16; ++it) {
        int i = tid + it * 1024;
        float s = roi_scores[i];
        sb[it] = (s >= MIN_RPN) ? __float_as_uint(s) : 0u;   // 0 never occurs for passing
        if (sb[it]) {
            int b = min((int)((sb[it] - BUCK_BASE) >> BUCK_SHIFT), NBUCK - 1);
            atomicAdd(&sCur[b], 1);
        }
    }
    __syncthreads();

    // ---- phase 2: exclusive scan in DESCENDING bucket order ----
    {
        int c[4], sum = 0;
        #pragma unroll
        for (int k = 0; k < 4; ++k) {
            int b = NBUCK - 1 - (tid * 4 + k);
            c[k] = sCur[b];
            sum += c[k];
        }
        int v = sum;
        #pragma unroll
        for (int off = 1; off < 32; off <<= 1) {
            int n = __shfl_up_sync(0xffffffffu, v, off);
            if (lane >= off) v += n;
        }
        if (lane == 31) s_wsum[wid] = v;
        __syncthreads();
        if (wid == 0) {
            int w = s_wsum[lane];
            #pragma unroll
            for (int off = 1; off < 32; off <<= 1) {
                int n = __shfl_up_sync(0xffffffffu, w, off);
                if (lane >= off) w += n;
            }
            s_wsum[lane] = w;
        }
        __syncthreads();
        int base = ((wid > 0) ? s_wsum[wid - 1] : 0) + (v - sum);  // exclusive for this thread
        #pragma unroll
        for (int k = 0; k < 4; ++k) {
            int b = NBUCK - 1 - (tid * 4 + k);
            sBase[b] = base;
            base += c[k];
        }
        if (tid == 0) s_M = min(s_wsum[31], CAP);
    }
    __syncthreads();
    const int M = s_M;
    if (tid == 0) g_M = M;
    #pragma unroll
    for (int k = 0; k < 4; ++k) {
        int b = tid * 4 + k;
        sCur[b] = sBase[b];                    // cursor = base
    }
    __syncthreads();

    // ---- phase 3: scatter keys from registers (no reload) ----
    #pragma unroll
    for (int it = 0; it < 16; ++it) {
        if (sb[it]) {
            int b = min((int)((sb[it] - BUCK_BASE) >> BUCK_SHIFT), NBUCK - 1);
            int pos = atomicAdd(&sCur[b], 1);
            if (pos < CAP)
                sKeys[pos] = ((u64)(0xFFFFFFFFu - sb[it]) << 32) | (unsigned)(tid + it * 1024);
        }
    }
    __syncthreads();

    // ---- phase 4: fixup multi-occupancy buckets (exact (score desc, idx asc) order) ----
    #pragma unroll
    for (int k = 0; k < 4; ++k) {
        int b = tid * 4 + k;
        int st = sBase[b];
        int en = (b > 0) ? sBase[b - 1] : M;   // descending layout: next-lower bucket's base
        if (en > CAP) en = CAP;
        if (en - st > 1) {
            for (int a = st + 1; a < en; ++a) { // insertion sort (ascending keys)
                u64 key = sKeys[a];
                int p = a - 1;
                while (p >= st && sKeys[p] > key) { sKeys[p + 1] = sKeys[p]; --p; }
                sKeys[p + 1] = key;
            }
        }
    }
    __syncthreads();

    // ---- phase 5: gather boxes in sorted order ----
    for (int t = tid; t < M; t += 1024) {
        u64 key = sKeys[t];
        int orig = (int)(key & 0xFFFFFFFFu);
        g_sortedIdx[t] = orig;
        float4 b = ((const float4*)det_boxes)[orig];   // [y1, x1, y2, x2]
        g_sortedBox[t] = b;
        g_areaArr[t] = (b.w - b.y) * (b.z - b.x);      // (x2-x1)*(y2-y1)
    }
}

// ================= kernel 2: warp-tiled suppression bitmask (transposed output) =================
__global__ void kMatrixW() {
    const int M  = g_M;
    const int Mw = (M + 31) >> 5;
    const int nT = Mw * Mw;
    const int lane = threadIdx.x & 31;
    const int gw = (blockIdx.x * blockDim.x + threadIdx.x) >> 5;
    const int nW = (gridDim.x * blockDim.x) >> 5;

    for (int t = gw; t < nT; t += nW) {
        int iw = t / Mw;
        int w  = t - iw * Mw;
        if (w < iw) continue;                    // triangle only

        int i = iw * 32 + lane;                  // this lane's row
        int jl = w * 32 + lane;                  // this lane's col (held for broadcast)
        float4 bi = g_sortedBox[min(i,  M - 1)];
        float  ai = g_areaArr [min(i,  M - 1)];
        float4 cb = g_sortedBox[min(jl, M - 1)];
        float  ca = g_areaArr [min(jl, M - 1)];

        unsigned bits = 0;
        #pragma unroll
        for (int jj = 0; jj < 32; ++jj) {
            float by1 = __shfl_sync(0xffffffffu, cb.x, jj);
            float bx1 = __shfl_sync(0xffffffffu, cb.y, jj);
            float by2 = __shfl_sync(0xffffffffu, cb.z, jj);
            float bx2 = __shfl_sync(0xffffffffu, cb.w, jj);
            float aj  = __shfl_sync(0xffffffffu, ca,   jj);
            int jc = w * 32 + jj;
            float iw_ = fminf(bi.w, bx2) - fmaxf(bi.y, bx1);
            float ih_ = fminf(bi.z, by2) - fmaxf(bi.x, by1);
            bool ok = (iw_ > 0.0f) && (ih_ > 0.0f) && (jc > i) && (jc < M);
            if (ok) {
                float inter = iw_ * ih_;
                float iou = inter / (ai + aj - inter + 1e-12f);
                ok = iou > NMS_THRESH;
            }
            bits |= (ok ? 1u : 0u) << jj;
        }
        if (i < M) g_matT[(size_t)w * CAP + i] = bits;   // coalesced store
    }
}

// ================= kernel 3: 64-box-chunk scan + select + GEMM + sort + outputs =================
#define NTHR 512
#define XW 4    /* prefetched cross iterations per warp (covers Mw <= 66) */

__global__ __launch_bounds__(NTHR, 1)
void kFinal(const float* __restrict__ roi_boxes,
            const float* __restrict__ det_boxes,
            const float* __restrict__ vis,
            const float* __restrict__ img_info,
            const float* __restrict__ txt,
            float* __restrict__ out) {
    __shared__ unsigned s_removed[RW];
    __shared__ unsigned s_keepw[RW];
    __shared__ unsigned s_flags[FLAG_WORDS];
    __shared__ int      s_scan[FLAG_WORDS];
    __shared__ int      s_wsum[16];
    __shared__ unsigned s_kmlo, s_kmhi;
    __shared__ int      s_cnt;
    __shared__ int      s_count;
    __shared__ int      s_selidx[KSEL];
    __shared__ float    S[KSEL][NUM_CATS];
    __shared__ float    s_key[KSEL];
    __shared__ int      s_src[KSEL];
    __shared__ unsigned char s_fgv[KSEL];

    const int tid  = threadIdx.x;
    const int lane = tid & 31;
    const int wid  = tid >> 5;          // 16 warps
    const int M    = g_M;
    const int Mw   = (M + 31) >> 5;
    const int Mc   = (M + 63) >> 6;     // 64-box chunks

    for (int t = tid; t < RW; t += NTHR) { s_removed[t] = 0; s_keepw[t] = 0; }
    for (int t = tid; t < FLAG_WORDS; t += NTHR) s_flags[t] = 0;
    if (tid == 0) s_cnt = 0;
    __syncthreads();

    // ---- chunked greedy NMS scan: prefetched cross words + uncapped fast resolve ----
    {
        unsigned d0lo = 0, d0hi = 0, d1hi = 0;   // warp0 diag registers
        if (wid == 0 && Mc > 0) {
            int r0 = lane, r1 = 32 + lane;
            if (r0 < M) { d0lo = g_matT[0 * CAP + r0];
                          if (1 < Mw) d0hi = g_matT[1 * CAP + r0]; }
            if (r1 < M && 1 < Mw) d1hi = g_matT[1 * CAP + r1];
        }

        for (int c = 0; c < Mc; ++c) {
            const int base = c * 64;
            const int lim  = M - base;                 // >0

            // ALL warps: prefetch this chunk's cross words (coalesced; in flight
            // during warp0's resolve). km masking after the barrier drops garbage.
            unsigned plo[XW], phi[XW];
            #pragma unroll
            for (int k = 0; k < XW; ++k) {
                int w = 2 * c + 2 + wid + 16 * k;
                plo[k] = 0; phi[k] = 0;
                if (w < Mw) {
                    plo[k] = g_matT[(size_t)w * CAP + base + lane];
                    phi[k] = g_matT[(size_t)w * CAP + base + 32 + lane];
                }
            }

            if (wid == 0) {
                unsigned valid0 = (lim >= 32) ? 0xFFFFFFFFu : ((1u << lim) - 1u);
                unsigned valid1 = (lim >= 64) ? 0xFFFFFFFFu
                                 : (lim > 32) ? ((1u << (lim - 32)) - 1u) : 0u;
                unsigned avail0 = valid0 & ~s_removed[2 * c];
                unsigned avail1 = valid1 & ~s_removed[2 * c + 1];
                unsigned kmlo, kmhi;
                int cnt = s_cnt;

                if (cnt + 64 <= MAX_DETS) {
                    // FAST path: no cap in the chain. Rows only carry bits j>i, so
                    // surviving avail == kept mask.
                    #pragma unroll
                    for (int i = 0; i < 32; ++i) {
                        unsigned rl = __shfl_sync(0xffffffffu, d0lo, i);
                        unsigned rh = __shfl_sync(0xffffffffu, d0hi, i);
                        if ((avail0 >> i) & 1u) { avail0 &= ~rl; avail1 &= ~rh; }
                    }
                    #pragma unroll
                    for (int i = 0; i < 32; ++i) {
                        unsigned rh = __shfl_sync(0xffffffffu, d1hi, i);
                        if ((avail1 >> i) & 1u) { avail1 &= ~rh; }
                    }
                    kmlo = avail0; kmhi = avail1;
                    cnt += __popc(kmlo) + __popc(kmhi);
                } else {
                    // CAPPED path (rare tail): original resolve with cnt in chain.
                    kmlo = 0; kmhi = 0;
                    #pragma unroll
                    for (int i = 0; i < 32; ++i) {
                        unsigned rl = __shfl_sync(0xffffffffu, d0lo, i);
                        unsigned rh = __shfl_sync(0xffffffffu, d0hi, i);
                        if (((avail0 >> i) & 1u) && cnt < MAX_DETS) {
                            kmlo |= 1u << i; ++cnt;
                            avail0 &= ~rl; avail1 &= ~rh;
                        }
                    }
                    #pragma unroll
                    for (int i = 0; i < 32; ++i) {
                        unsigned rh = __shfl_sync(0xffffffffu, d1hi, i);
                        if (((avail1 >> i) & 1u) && cnt < MAX_DETS) {
                            kmhi |= 1u << i; ++cnt;
                            avail1 &= ~rh;
                        }
                    }
                }
                if (lane == 0) {
                    s_keepw[2 * c] = kmlo;
                    if (2 * c + 1 < Mw) s_keepw[2 * c + 1] = kmhi;
                    s_kmlo = kmlo; s_kmhi = kmhi; s_cnt = cnt;
                }
                // prefetch next chunk's diag
                d0lo = d0hi = d1hi = 0;
                if (c + 1 < Mc) {
                    int nb = (c + 1) * 64;
                    int r0 = nb + lane, r1 = nb + 32 + lane;
                    int w0 = 2 * c + 2, w1 = 2 * c + 3;
                    if (r0 < M) { d0lo = g_matT[(size_t)w0 * CAP + r0];
                                  if (w1 < Mw) d0hi = g_matT[(size_t)w1 * CAP + r0]; }
                    if (r1 < M && w1 < Mw) d1hi = g_matT[(size_t)w1 * CAP + r1];
                }
            }
            __syncthreads();

            const unsigned kmlo = s_kmlo, kmhi = s_kmhi;
            const int stop = (s_cnt >= MAX_DETS);      // read strictly between the two barriers
            if (kmlo | kmhi) {
                const unsigned mlo = ((kmlo >> lane) & 1u) ? 0xFFFFFFFFu : 0u;
                const unsigned mhi = ((kmhi >> lane) & 1u) ? 0xFFFFFFFFu : 0u;
                #pragma unroll
                for (int k = 0; k < XW; ++k) {
                    int w = 2 * c + 2 + wid + 16 * k;
                    if (w < Mw) {
                        unsigned v = (plo[k] & mlo) | (phi[k] & mhi);
                        unsigned red = __reduce_or_sync(0xffffffffu, v);
                        if (lane == 0 && red) s_removed[w] |= red;
                    }
                }
                // leftover words beyond the prefetch window (only if Mw > 66)
                for (int w = 2 * c + 2 + wid + 16 * XW; w < Mw; w += 16) {
                    unsigned v = 0;
                    if ((kmlo >> lane) & 1u) v |= g_matT[(size_t)w * CAP + base + lane];
                    if ((kmhi >> lane) & 1u) v |= g_matT[(size_t)w * CAP + base + 32 + lane];
                    unsigned red = __reduce_or_sync(0xffffffffu, v);
                    if (lane == 0 && red) s_removed[w] |= red;
                }
            }
            __syncthreads();
            if (stop) break;                           // uniform; later s_keepw words stay 0
        }
    }

    // ---- valid flags on ORIGINAL indices ----
    const float sy = img_info[4];    // image_info[2][0]
    const float sx = img_info[5];    // image_info[2][1]
    for (int t = tid; t < M; t += NTHR) {
        if ((s_keepw[t >> 5] >> (t & 31)) & 1u) {
            int orig = g_sortedIdx[t];
            float4 rb = ((const float4*)roi_boxes)[orig];
            bool allz = (rb.x == 0.f && rb.y == 0.f && rb.z == 0.f && rb.w == 0.f);
            float4 db = g_sortedBox[t];
            float area = (db.z / sy - db.x / sy) * (db.w / sx - db.y / sx);
            if (!allz && area > MIN_AREA)
                atomicOr(&s_flags[orig >> 5], 1u << (orig & 31));
        }
    }
    __syncthreads();

    // ---- inclusive prefix scan over 512 popcounts (warp shuffles) ----
    {
        int v = __popc(s_flags[tid]);
        #pragma unroll
        for (int off = 1; off < 32; off <<= 1) {
            int n = __shfl_up_sync(0xffffffff, v, off);
            if (lane >= off) v += n;
        }
        if (lane == 31) s_wsum[wid] = v;
        __syncthreads();
        if (wid == 0 && lane < 16) {
            int w = s_wsum[lane];
            #pragma unroll
            for (int off = 1; off < 16; off <<= 1) {
                int n = __shfl_up_sync(0x0000ffff, w, off);
                if (lane >= off) w += n;
            }
            s_wsum[lane] = w;
        }
        __syncthreads();
        int basew = (wid > 0) ? s_wsum[wid - 1] : 0;
        s_scan[tid] = basew + v;                         // inclusive
        if (tid == 0) s_count = s_wsum[15];
    }
    if (tid < KSEL) s_selidx[tid] = 0;                   // jnp.nonzero fill_value = 0
    __syncthreads();
    {
        int excl = s_scan[tid] - __popc(s_flags[tid]);
        if (excl < KSEL) {
            unsigned f = s_flags[tid];
            int r = excl;
            while (f && r < KSEL) {
                int b = __ffs(f) - 1; f &= f - 1;
                s_selidx[r] = tid * 32 + b;
                ++r;
            }
        }
    }
    __syncthreads();

    // ---- GEMM: S[25][65] = vis[idx] @ txt^T  (warp-per-2-rows, K split across lanes) ----
    if (wid < 13) {
        const int r0 = 2 * wid;
        const int r1 = r0 + 1;
        const bool has1 = (r1 < KSEL);
        const float4* v0 = (const float4*)(vis + (size_t)s_selidx[r0] * FEAT);
        const float4* v1 = (const float4*)(vis + (size_t)s_selidx[has1 ? r1 : r0] * FEAT);
        float4 a0[4], a1[4];
        #pragma unroll
        for (int q = 0; q < 4; ++q) {
            a0[q] = v0[q * 32 + lane];                   // coalesced: 32 lanes = 512B
            a1[q] = v1[q * 32 + lane];
        }
        for (int cc = 0; cc < NUM_CATS; ++cc) {
            const float4* tf = (const float4*)(txt + (size_t)cc * FEAT);
            float p0 = 0.f, p1 = 0.f;
            #pragma unroll
            for (int q = 0; q < 4; ++q) {
                float4 b = tf[q * 32 + lane];            // coalesced
                p0 += a0[q].x * b.x + a0[q].y * b.y + a0[q].z * b.z + a0[q].w * b.w;
                p1 += a1[q].x * b.x + a1[q].y * b.y + a1[q].z * b.z + a1[q].w * b.w;
            }
            #pragma unroll
            for (int off = 16; off; off >>= 1) {
                p0 += __shfl_xor_sync(0xffffffff, p0, off);
                p1 += __shfl_xor_sync(0xffffffff, p1, off);
            }
            if (lane == 0) {
                S[r0][cc] = p0;
                if (has1) S[r1][cc] = p1;
            }
        }
    }
    __syncthreads();

    // ---- per-row max / argmax, fg, sort key ----
    if (tid < KSEL) {
        float mx = S[tid][0]; int am = 0;
        for (int cc = 1; cc < NUM_CATS; ++cc) {
            float v = S[tid][cc];
            if (v > mx) { mx = v; am = cc; }
        }
        bool rv = tid < min(s_count, KSEL);
        bool fg = rv && (am != 0);
        s_fgv[tid] = fg ? 1 : 0;
        s_key[tid] = fg ? mx : __int_as_float(0xff800000);   // -inf
    }
    __syncthreads();

    // ---- stable descending argsort via rank ----
    if (tid < KSEL) {
        float k = s_key[tid];
        int rank = 0;
        for (int j = 0; j < KSEL; ++j) {
            float kj = s_key[j];
            if (kj > k || (kj == k && j < tid)) ++rank;
        }
        s_src[rank] = tid;
    }
    __syncthreads();

    // ---- outputs: scores (25x64) | bboxes (25x4) | mask (25) ----
    for (int p = tid; p < KSEL * (NUM_CATS - 1); p += NTHR) {
        int row = p / (NUM_CATS - 1), cc = p - row * (NUM_CATS - 1);
        int s = s_src[row];
        out[p] = s_fgv[s] ? S[s][cc + 1] : 0.f;
    }
    if (tid < KSEL) {
        int s = s_src[tid];
        bool m = s_fgv[s] != 0;
        float4 db = ((const float4*)det_boxes)[s_selidx[s]];
        float xmin = db.y / sx, ymin = db.x / sy, xmax = db.w / sx, ymax = db.z / sy;
        float* o = out + KSEL * (NUM_CATS - 1) + tid * 4;
        o[0] = m ? xmin : 0.f;
        o[1] = m ? ymin : 0.f;
        o[2] = m ? xmax : 0.f;
        o[3] = m ? ymax : 0.f;
        out[KSEL * (NUM_CATS - 1) + KSEL * 4 + tid] = m ? 1.f : 0.f;
    }
}

// ---------------- launch ----------------
extern "C" void kernel_launch(void* const* d_in, const int* in_sizes, int n_in,
                              void* d_out, int out_size) {
    const float* roi_boxes  = (const float*)d_in[0];
    const float* roi_scores = (const float*)d_in[1];
    const float* det_boxes  = (const float*)d_in[2];
    /* d_in[3]: detection_masks — unused by reference outputs */
    const float* vis        = (const float*)d_in[4];
    const float* img_info   = (const float*)d_in[5];
    const float* txt        = (const float*)d_in[6];
    float* out = (float*)d_out;

    static int attr_done = 0;
    if (!attr_done) {
        cudaFuncSetAttribute(kPrep, cudaFuncAttributeMaxDynamicSharedMemorySize, CAP * 8);
        attr_done = 1;
    }
    kPrep<<<1, 1024, CAP * 8>>>(roi_scores, det_boxes);
    kMatrixW<<<352, 256>>>();
    kFinal<<<1, NTHR>>>(roi_boxes, det_boxes, vis, img_info, txt, out);
}